// round 12
// baseline (speedup 1.0000x reference)
#include <cuda_runtime.h>
#include <cuda_bf16.h>
#include <cstdint>
#include <cstddef>

#define THREADS   256
#define BM        32
#define AS        264    // A row stride (bf16): 528B rows, ldmatrix conflict-free
#define BS        40     // B row stride (bf16): 80B rows, conflict-free
#define B_TARGETS 4096
#define L1_ROWS   (B_TARGETS * 11)   // 45056

__device__ __align__(256) float         g_h1[L1_ROWS * 128];
__device__ __align__(256) __nv_bfloat16 g_Ah[L1_ROWS * 256];   // 23 MB
__device__ __align__(256) __nv_bfloat16 g_Al[L1_ROWS * 256];   // 23 MB
__device__ __align__(256) __nv_bfloat16 g_W0h[128 * 256];
__device__ __align__(256) __nv_bfloat16 g_W0l[128 * 256];
__device__ __align__(256) __nv_bfloat16 g_W1h[128 * 256];
__device__ __align__(256) __nv_bfloat16 g_W1l[128 * 256];

typedef unsigned long long u64;

__device__ __forceinline__ float bfrt(float x) {
    float r;
    asm("{\n\t.reg .b16 t;\n\tcvt.rn.bf16.f32 t, %1;\n\tcvt.f32.bf16 %0, t;\n\t}"
        : "=f"(r) : "f"(x));
    return r;
}
__device__ __forceinline__ uint32_t pk_bf16(float x, float y) {
    uint32_t r;
    asm("{\n\t.reg .b16 l, h;\n\tcvt.rn.bf16.f32 l, %1;\n\tcvt.rn.bf16.f32 h, %2;\n\t"
        "mov.b32 %0, {l, h};\n\t}" : "=r"(r) : "f"(x), "f"(y));
    return r;
}
__device__ __forceinline__ void add2(u64& d, u64 a) {
    asm("add.rn.f32x2 %0, %1, %0;" : "+l"(d) : "l"(a));
}
__device__ __forceinline__ u64 pack2(float lo, float hi) {
    u64 r; asm("mov.b64 %0, {%1, %2};" : "=l"(r) : "f"(lo), "f"(hi)); return r;
}
__device__ __forceinline__ float2 unpack2(u64 v) {
    float2 r; asm("mov.b64 {%0, %1}, %2;" : "=f"(r.x), "=f"(r.y) : "l"(v)); return r;
}
__device__ __forceinline__ u64 mul2(u64 a, u64 b) {
    u64 r; asm("mul.rn.f32x2 %0, %1, %2;" : "=l"(r) : "l"(a), "l"(b)); return r;
}
__device__ __forceinline__ void cpa8(uint32_t dst, const void* src) {
    asm volatile("cp.async.ca.shared.global [%0], [%1], 8;" :: "r"(dst), "l"(src));
}
__device__ __forceinline__ void cpa_commit() {
    asm volatile("cp.async.commit_group;");
}
template <int N>
__device__ __forceinline__ void cpa_wait() {
    asm volatile("cp.async.wait_group %0;" :: "n"(N));
}
__device__ __forceinline__ void ldsm4(uint32_t* r, uint32_t addr) {
    asm volatile("ldmatrix.sync.aligned.m8n8.x4.shared.b16 {%0,%1,%2,%3}, [%4];"
                 : "=r"(r[0]), "=r"(r[1]), "=r"(r[2]), "=r"(r[3]) : "r"(addr));
}
__device__ __forceinline__ void mma_bf16(float* c, const uint32_t* a,
                                         uint32_t b0, uint32_t b1) {
    asm volatile("mma.sync.aligned.m16n8k16.row.col.f32.bf16.bf16.f32 "
                 "{%0,%1,%2,%3}, {%4,%5,%6,%7}, {%8,%9}, {%0,%1,%2,%3};"
                 : "+f"(c[0]), "+f"(c[1]), "+f"(c[2]), "+f"(c[3])
                 : "r"(a[0]), "r"(a[1]), "r"(a[2]), "r"(a[3]), "r"(b0), "r"(b1));
}

__global__ void prep_w(const float* __restrict__ W0, const float* __restrict__ W1) {
    const int i = blockIdx.x * 256 + threadIdx.x;      // 0..32767
    const float a = W0[i], b = W1[i];
    g_W0h[i] = __float2bfloat16(a);
    g_W0l[i] = __float2bfloat16(a - bfrt(a));
    g_W1h[i] = __float2bfloat16(b);
    g_W1l[i] = __float2bfloat16(b - bfrt(b));
}

// Pure gather: one warp per level-1 row j. Builds [self || mean(25 nbrs)]
// and writes the bf16 hi/lo A row to g_Ah/g_Al ([j][256] linear).
// Low regs + no smem -> high occupancy -> deep load pipelining (DRAM-bound).
__global__ __launch_bounds__(THREADS, 6)
void gather0(const float* __restrict__ feat,
             const int*   __restrict__ nodes,
             const int*   __restrict__ nbr1,
             const int*   __restrict__ nbr0)
{
    const int warp = (blockIdx.x * THREADS + threadIdx.x) >> 5;
    const int lane = threadIdx.x & 31;
    const int j    = warp;                 // level-1 row, grid sized exactly
    const int b    = j / 11;
    const int col  = j - b * 11;
    const int sidx = (col == 0) ? __ldg(&nodes[b])
                                : __ldg(&nbr1[b * 10 + col - 1]);

    const float4 self = ((const float4*)(feat + (size_t)sidx * 128))[lane];
    const int myidx = (lane < 25) ? __ldg(&nbr0[(size_t)j * 25 + lane]) : 0;

    u64 p01 = 0, p23 = 0, q01 = 0, q23 = 0;
    #pragma unroll
    for (int s = 0; s < 25; ++s) {
        const int ni = __shfl_sync(0xffffffffu, myidx, s);
        const float4 v = ((const float4*)(feat + (size_t)ni * 128))[lane];
        if (s & 1) { add2(q01, pack2(v.x, v.y)); add2(q23, pack2(v.z, v.w)); }
        else       { add2(p01, pack2(v.x, v.y)); add2(p23, pack2(v.z, v.w)); }
    }
    add2(p01, q01); add2(p23, q23);
    const u64 sc = pack2(1.0f / 25.0f, 1.0f / 25.0f);
    const float2 m01 = unpack2(mul2(p01, sc));
    const float2 m23 = unpack2(mul2(p23, sc));

    __nv_bfloat16* rowH = g_Ah + (size_t)j * 256;
    __nv_bfloat16* rowL = g_Al + (size_t)j * 256;
    *(uint2*)(rowH + 4 * lane) =
        make_uint2(pk_bf16(self.x, self.y), pk_bf16(self.z, self.w));
    *(uint2*)(rowL + 4 * lane) =
        make_uint2(pk_bf16(self.x - bfrt(self.x), self.y - bfrt(self.y)),
                   pk_bf16(self.z - bfrt(self.z), self.w - bfrt(self.w)));
    *(uint2*)(rowH + 128 + 4 * lane) =
        make_uint2(pk_bf16(m01.x, m01.y), pk_bf16(m23.x, m23.y));
    *(uint2*)(rowL + 128 + 4 * lane) =
        make_uint2(pk_bf16(m01.x - bfrt(m01.x), m01.y - bfrt(m01.y)),
                   pk_bf16(m23.x - bfrt(m23.x), m23.y - bfrt(m23.y)));
}

// HMMA tile kernel (proven R11 body).
// LAYER 1: fused gather of targets from g_h1 (self + mean of 10).
// LAYER 2: A rows precomputed in g_Ah/g_Al -> straight coalesced copy.
// BM=32 rows/block; 8 warps each own 16 output cols over all rows.
template <int LAYER>
__global__ __launch_bounds__(THREADS, 3)
void sage_hmma(const float* __restrict__ src,
               const __nv_bfloat16* __restrict__ gAh,
               const __nv_bfloat16* __restrict__ gAl,
               const __nv_bfloat16* __restrict__ Wh,   // [128 n][256 k]
               const __nv_bfloat16* __restrict__ Wl,
               const float* __restrict__ bias,
               float*       __restrict__ out)          // [rows][128]
{
    extern __shared__ char sm[];
    __nv_bfloat16* Ah  = (__nv_bfloat16*)sm;           // BM*AS
    __nv_bfloat16* Al  = Ah + BM * AS;                 // BM*AS
    __nv_bfloat16* Bsm = Al + BM * AS;                 // [2 hl][128][BS]
    float* sBias = (float*)(Bsm + 2 * 128 * BS);       // 128
    float* red   = sBias + 128;                        // [8][BM]
    float* sInv  = red + 8 * BM;                       // BM

    const int tid  = threadIdx.x;
    const int warp = tid >> 5;
    const int lane = tid & 31;
    const int m0   = blockIdx.x * BM;
    const int Nb   = warp * 16;

    const uint32_t uAh = (uint32_t)__cvta_generic_to_shared(Ah);
    const uint32_t uAl = (uint32_t)__cvta_generic_to_shared(Al);
    const uint32_t uB  = (uint32_t)__cvta_generic_to_shared(Bsm);

    // B chunk 0 (32 k-cols, hi+lo) via cp.async — lands during the A fill.
    {
        #pragma unroll
        for (int t = 0; t < 8; ++t) {
            const int e  = tid + t * THREADS;   // 0..2047
            const int hl = e >> 10;
            const int n  = (e >> 3) & 127;
            const int pc = e & 7;               // 8B piece within 32 cols
            cpa8(uB + (uint32_t)(hl * 128 * BS + n * BS + pc * 4) * 2,
                 (hl ? Wl : Wh) + n * 256 + pc * 4);
        }
        cpa_commit();
    }

    if (tid < 128) sBias[tid] = bias[tid];

    // ---------------- A fill ------------------------------------------------
    if (LAYER == 2) {
        // precomputed rows: 1 LDG.128 + 1 STS.128 per lane per row per buffer
        #pragma unroll
        for (int r = 0; r < 4; ++r) {
            const int mL = warp * 4 + r;
            const size_t j = (size_t)(m0 + mL) * 256;
            const uint4 h = *(const uint4*)(gAh + j + 8 * lane);
            const uint4 l = *(const uint4*)(gAl + j + 8 * lane);
            *(uint4*)(Ah + mL * AS + 8 * lane) = h;
            *(uint4*)(Al + mL * AS + 8 * lane) = l;
        }
    } else {
        // fused layer-1 gather from g_h1, rows in pairs (R11-proven)
        auto storeA = [&](int mL, float4 s4, float2 m01, float2 m23) {
            __nv_bfloat16* rowH = Ah + mL * AS;
            __nv_bfloat16* rowL = Al + mL * AS;
            *(uint2*)(rowH + 4 * lane) =
                make_uint2(pk_bf16(s4.x, s4.y), pk_bf16(s4.z, s4.w));
            *(uint2*)(rowL + 4 * lane) =
                make_uint2(pk_bf16(s4.x - bfrt(s4.x), s4.y - bfrt(s4.y)),
                           pk_bf16(s4.z - bfrt(s4.z), s4.w - bfrt(s4.w)));
            *(uint2*)(rowH + 128 + 4 * lane) =
                make_uint2(pk_bf16(m01.x, m01.y), pk_bf16(m23.x, m23.y));
            *(uint2*)(rowL + 128 + 4 * lane) =
                make_uint2(pk_bf16(m01.x - bfrt(m01.x), m01.y - bfrt(m01.y)),
                           pk_bf16(m23.x - bfrt(m23.x), m23.y - bfrt(m23.y)));
        };
        #pragma unroll 1
        for (int r0 = 0; r0 < 4; r0 += 2) {
            const int mLa = warp * 4 + r0;
            const int mLb = mLa + 1;
            const float* baseA = src + (size_t)(m0 + mLa) * (11 * 128);
            const float* baseB = src + (size_t)(m0 + mLb) * (11 * 128);
            const float4 selfA = ((const float4*)baseA)[lane];
            const float4 selfB = ((const float4*)baseB)[lane];
            u64 pa01 = 0, pa23 = 0, qa01 = 0, qa23 = 0;
            u64 pb01 = 0, pb23 = 0, qb01 = 0, qb23 = 0;
            #pragma unroll
            for (int s = 1; s <= 10; ++s) {
                float4 va = ((const float4*)(baseA + s * 128))[lane];
                float4 vb = ((const float4*)(baseB + s * 128))[lane];
                if (s & 1) {
                    add2(qa01, pack2(va.x, va.y)); add2(qa23, pack2(va.z, va.w));
                    add2(qb01, pack2(vb.x, vb.y)); add2(qb23, pack2(vb.z, vb.w));
                } else {
                    add2(pa01, pack2(va.x, va.y)); add2(pa23, pack2(va.z, va.w));
                    add2(pb01, pack2(vb.x, vb.y)); add2(pb23, pack2(vb.z, vb.w));
                }
            }
            const u64 scale = pack2(0.1f, 0.1f);
            add2(pa01, qa01); add2(pa23, qa23);
            add2(pb01, qb01); add2(pb23, qb23);
            storeA(mLa, selfA, unpack2(mul2(pa01, scale)), unpack2(mul2(pa23, scale)));
            storeA(mLb, selfB, unpack2(mul2(pb01, scale)), unpack2(mul2(pb23, scale)));
        }
    }

    cpa_wait<0>();
    __syncthreads();                 // A tile + B chunk 0 published

    // ---------------- HMMA mainloop: single B buffer + reg prefetch --------
    float acc[2][2][4];              // [mt 16-row][8-col group][frag]
    #pragma unroll
    for (int mt = 0; mt < 2; ++mt)
        #pragma unroll
        for (int g = 0; g < 2; ++g)
            #pragma unroll
            for (int c = 0; c < 4; ++c) acc[mt][g][c] = 0.f;

    const int li = lane >> 3, lr = lane & 7;
    int4 stg4[4];

    #pragma unroll 1
    for (int kc = 0; kc < 8; ++kc) {
        if (kc < 7) {                // prefetch next chunk into regs (hi, lo)
            #pragma unroll
            for (int t = 0; t < 2; ++t) {
                const int e = tid + t * THREADS;  // 0..511
                const int n = e >> 2, pc = e & 3;
                stg4[t]     = *(const int4*)(Wh + n * 256 + (kc + 1) * 32 + pc * 8);
                stg4[2 + t] = *(const int4*)(Wl + n * 256 + (kc + 1) * 32 + pc * 8);
            }
        }
        #pragma unroll
        for (int s = 0; s < 2; ++s) {
            const int k0g = kc * 32 + s * 16;
            uint32_t Ahf[2][4], Alf[2][4];
            #pragma unroll
            for (int mt = 0; mt < 2; ++mt) {
                const int row = mt * 16 + (li & 1) * 8 + lr;
                const int col = k0g + (li >> 1) * 8;
                const uint32_t off = (uint32_t)(row * AS + col) * 2;
                ldsm4(Ahf[mt], uAh + off);
                ldsm4(Alf[mt], uAl + off);
            }
            uint32_t Bhf[4], Blf[4];
            {
                const int n  = Nb + (li >> 1) * 8 + lr;
                const int kk = s * 16 + (li & 1) * 8;
                const uint32_t off = (uint32_t)(n * BS + kk) * 2;
                ldsm4(Bhf, uB + off);
                ldsm4(Blf, uB + (uint32_t)(128 * BS * 2) + off);
            }
            #pragma unroll
            for (int mt = 0; mt < 2; ++mt)
                #pragma unroll
                for (int h = 0; h < 2; ++h) {
                    float* c = acc[mt][h];
                    mma_bf16(c, Ahf[mt], Bhf[2 * h], Bhf[2 * h + 1]);
                    mma_bf16(c, Ahf[mt], Blf[2 * h], Blf[2 * h + 1]);
                    mma_bf16(c, Alf[mt], Bhf[2 * h], Bhf[2 * h + 1]);
                }
        }
        if (kc < 7) {
            __syncthreads();         // all warps done reading B chunk kc
            #pragma unroll
            for (int t = 0; t < 2; ++t) {
                const int e = tid + t * THREADS;
                const int n = e >> 2, pc = e & 3;
                *(int4*)(Bsm + n * BS + pc * 8)            = stg4[t];
                *(int4*)(Bsm + 128 * BS + n * BS + pc * 8) = stg4[2 + t];
            }
            __syncthreads();         // chunk kc+1 published
        }
    }

    // ---------------- epilogue: bias + relu + row l2-norm + store ----------
    const int rg = lane >> 2;
    const int lc = (lane & 3) * 2;

    float bb[2][2];
    #pragma unroll
    for (int g = 0; g < 2; ++g) {
        bb[g][0] = sBias[Nb + g * 8 + lc];
        bb[g][1] = sBias[Nb + g * 8 + lc + 1];
    }

    #pragma unroll
    for (int mt = 0; mt < 2; ++mt)
        #pragma unroll
        for (int rh = 0; rh < 2; ++rh) {
            float ss = 0.f;
            #pragma unroll
            for (int g = 0; g < 2; ++g) {
                float v0 = fmaxf(acc[mt][g][2 * rh]     + bb[g][0], 0.f);
                float v1 = fmaxf(acc[mt][g][2 * rh + 1] + bb[g][1], 0.f);
                acc[mt][g][2 * rh]     = v0;
                acc[mt][g][2 * rh + 1] = v1;
                ss += v0 * v0 + v1 * v1;
            }
            ss += __shfl_xor_sync(0xffffffffu, ss, 1);
            ss += __shfl_xor_sync(0xffffffffu, ss, 2);
            if ((lane & 3) == 0)
                red[warp * BM + mt * 16 + rh * 8 + rg] = ss;
        }
    __syncthreads();

    if (tid < BM) {
        float t = 0.f;
        #pragma unroll
        for (int n = 0; n < 8; ++n) t += red[n * BM + tid];
        sInv[tid] = 1.0f / fmaxf(sqrtf(t), 1e-12f);
    }
    __syncthreads();

    #pragma unroll
    for (int mt = 0; mt < 2; ++mt)
        #pragma unroll
        for (int rh = 0; rh < 2; ++rh) {
            const int row = mt * 16 + rh * 8 + rg;
            const float inv = sInv[row];
            float* orow = out + (size_t)(m0 + row) * 128 + Nb + lc;
            #pragma unroll
            for (int g = 0; g < 2; ++g)
                *(float2*)(orow + g * 8) =
                    make_float2(acc[mt][g][2 * rh] * inv,
                                acc[mt][g][2 * rh + 1] * inv);
        }
}

extern "C" void kernel_launch(void* const* d_in, const int* in_sizes, int n_in,
                              void* d_out, int out_size)
{
    (void)in_sizes; (void)n_in; (void)out_size;

    const float* features = (const float*)d_in[0];
    const float* W0       = (const float*)d_in[1];
    const float* b0       = (const float*)d_in[2];
    const float* W1       = (const float*)d_in[3];
    const float* b1       = (const float*)d_in[4];
    const int*   nodes    = (const int*)d_in[5];
    const int*   nbr1     = (const int*)d_in[6];
    const int*   nbr0     = (const int*)d_in[7];
    float*       out      = (float*)d_out;

    // smem: 2*32*264*2 + 2*128*40*2 + 512 + 8*32*4 + 32*4 = 55936 B -> occ 3
    const int SMEM = 2 * BM * AS * 2 + 2 * 128 * BS * 2 + 512
                     + 8 * BM * 4 + BM * 4;

    cudaFuncSetAttribute(sage_hmma<2>,
                         cudaFuncAttributeMaxDynamicSharedMemorySize, SMEM);
    cudaFuncSetAttribute(sage_hmma<2>,
                         cudaFuncAttributePreferredSharedMemoryCarveout, 100);
    cudaFuncSetAttribute(sage_hmma<1>,
                         cudaFuncAttributeMaxDynamicSharedMemorySize, SMEM);
    cudaFuncSetAttribute(sage_hmma<1>,
                         cudaFuncAttributePreferredSharedMemoryCarveout, 100);

    float *h1; __nv_bfloat16 *w0h, *w0l, *w1h, *w1l, *ah, *al;
    cudaGetSymbolAddress((void**)&h1,  g_h1);
    cudaGetSymbolAddress((void**)&ah,  g_Ah);
    cudaGetSymbolAddress((void**)&al,  g_Al);
    cudaGetSymbolAddress((void**)&w0h, g_W0h);
    cudaGetSymbolAddress((void**)&w0l, g_W0l);
    cudaGetSymbolAddress((void**)&w1h, g_W1h);
    cudaGetSymbolAddress((void**)&w1l, g_W1l);

    prep_w<<<128, 256>>>(W0, W1);
    gather0<<<L1_ROWS / 8, THREADS>>>(features, nodes, nbr1, nbr0);
    sage_hmma<2><<<L1_ROWS / BM, THREADS, SMEM>>>(
        nullptr, ah, al, w0h, w0l, b0, h1);
    sage_hmma<1><<<B_TARGETS / BM, THREADS, SMEM>>>(
        h1, nullptr, nullptr, w1h, w1l, b1, out);
}

// round 14
// speedup vs baseline: 1.1933x; 1.1933x over previous
#include <cuda_runtime.h>
#include <cuda_bf16.h>
#include <cstdint>
#include <cstddef>

#define THREADS   256
#define AS        264    // A row stride (bf16): 528B rows, ldmatrix conflict-free
#define BS        40     // B row stride (bf16): 80B rows, ldmatrix conflict-free
#define BWB       2560   // bytes per warp B buffer (2 hl * 16 n * 80B)
#define B_TARGETS 4096
#define L1_ROWS   (B_TARGETS * 11)   // 45056

__device__ __align__(256) float         g_h1[L1_ROWS * 128];
__device__ __align__(256) __nv_bfloat16 g_W0h[128 * 256];
__device__ __align__(256) __nv_bfloat16 g_W0l[128 * 256];
__device__ __align__(256) __nv_bfloat16 g_W1h[128 * 256];
__device__ __align__(256) __nv_bfloat16 g_W1l[128 * 256];

typedef unsigned long long u64;

__device__ __forceinline__ float bfrt(float x) {
    float r;
    asm("{\n\t.reg .b16 t;\n\tcvt.rn.bf16.f32 t, %1;\n\tcvt.f32.bf16 %0, t;\n\t}"
        : "=f"(r) : "f"(x));
    return r;
}
__device__ __forceinline__ uint32_t pk_bf16(float x, float y) {
    uint32_t r;
    asm("{\n\t.reg .b16 l, h;\n\tcvt.rn.bf16.f32 l, %1;\n\tcvt.rn.bf16.f32 h, %2;\n\t"
        "mov.b32 %0, {l, h};\n\t}" : "=r"(r) : "f"(x), "f"(y));
    return r;
}
__device__ __forceinline__ void add2(u64& d, u64 a) {
    asm("add.rn.f32x2 %0, %1, %0;" : "+l"(d) : "l"(a));
}
__device__ __forceinline__ u64 pack2(float lo, float hi) {
    u64 r; asm("mov.b64 %0, {%1, %2};" : "=l"(r) : "f"(lo), "f"(hi)); return r;
}
__device__ __forceinline__ float2 unpack2(u64 v) {
    float2 r; asm("mov.b64 {%0, %1}, %2;" : "=f"(r.x), "=f"(r.y) : "l"(v)); return r;
}
__device__ __forceinline__ u64 mul2(u64 a, u64 b) {
    u64 r; asm("mul.rn.f32x2 %0, %1, %2;" : "=l"(r) : "l"(a), "l"(b)); return r;
}
__device__ __forceinline__ void cp16(uint32_t dst, const void* src) {
    asm volatile("cp.async.cg.shared.global [%0], [%1], 16;" :: "r"(dst), "l"(src));
}
__device__ __forceinline__ void cpa_commit() {
    asm volatile("cp.async.commit_group;");
}
template <int N>
__device__ __forceinline__ void cpa_wait() {
    asm volatile("cp.async.wait_group %0;" :: "n"(N));
}
__device__ __forceinline__ void ldsm4(uint32_t* r, uint32_t addr) {
    asm volatile("ldmatrix.sync.aligned.m8n8.x4.shared.b16 {%0,%1,%2,%3}, [%4];"
                 : "=r"(r[0]), "=r"(r[1]), "=r"(r[2]), "=r"(r[3]) : "r"(addr));
}
__device__ __forceinline__ void mma_bf16(float* c, const uint32_t* a,
                                         uint32_t b0, uint32_t b1) {
    asm volatile("mma.sync.aligned.m16n8k16.row.col.f32.bf16.bf16.f32 "
                 "{%0,%1,%2,%3}, {%4,%5,%6,%7}, {%8,%9}, {%0,%1,%2,%3};"
                 : "+f"(c[0]), "+f"(c[1]), "+f"(c[2]), "+f"(c[3])
                 : "r"(a[0]), "r"(a[1]), "r"(a[2]), "r"(a[3]), "r"(b0), "r"(b1));
}

// Pre-split W0/W1 into bf16 hi/lo. Vectorized: grid 32 x 256, 1 float4 each.
__global__ void prep_w(const float* __restrict__ W0, const float* __restrict__ W1) {
    const int i = blockIdx.x * 256 + threadIdx.x;      // 0..8191 float4 groups
    const float4 a = ((const float4*)W0)[i];
    const float4 b = ((const float4*)W1)[i];
    *(uint2*)(g_W0h + 4 * i) =
        make_uint2(pk_bf16(a.x, a.y), pk_bf16(a.z, a.w));
    *(uint2*)(g_W0l + 4 * i) =
        make_uint2(pk_bf16(a.x - bfrt(a.x), a.y - bfrt(a.y)),
                   pk_bf16(a.z - bfrt(a.z), a.w - bfrt(a.w)));
    *(uint2*)(g_W1h + 4 * i) =
        make_uint2(pk_bf16(b.x, b.y), pk_bf16(b.z, b.w));
    *(uint2*)(g_W1l + 4 * i) =
        make_uint2(pk_bf16(b.x - bfrt(b.x), b.y - bfrt(b.y)),
                   pk_bf16(b.z - bfrt(b.z), b.w - bfrt(b.w)));
}

// Fused tile: register-LDG gather (paired rows) -> bf16 hi/lo A -> HMMA
// (3-product bf16 split, fp32 accum) -> bias+relu+row-l2norm -> out.
// 8 warps each own 16 output cols. B: per-warp private cp.async double buffer
// (warp-local wait_group+syncwarp, NO block barriers in the mainloop).
// LAYER 0: rows = level-1 nodes (self feat || mean of 25 nbr feats).
// LAYER 1: rows = targets       (h1[b,0]   || mean of h1[b,1..10]).
template <int LAYER, int BM>
__global__ __launch_bounds__(THREADS, 3)
void sage_hmma(const float* __restrict__ src,
               const int*   __restrict__ nodes,
               const int*   __restrict__ nbr1,
               const int*   __restrict__ nbr0,
               const __nv_bfloat16* __restrict__ Wh,   // [128 n][256 k]
               const __nv_bfloat16* __restrict__ Wl,
               const float* __restrict__ bias,
               float*       __restrict__ out)          // [rows][128]
{
    constexpr int MT = BM / 16;        // 16-row tiles per block
    constexpr int R  = BM / 8;         // gather rows per warp

    extern __shared__ char sm[];
    __nv_bfloat16* Ah  = (__nv_bfloat16*)sm;           // BM*AS
    __nv_bfloat16* Al  = Ah + BM * AS;                 // BM*AS
    char* Bw = (char*)(Al + BM * AS);                  // 8 warps * 2 bufs * BWB
    float* sBias = (float*)(Bw + 8 * 2 * BWB);         // 128
    float* red   = sBias + 128;                        // [8][BM]
    float* sInv  = red + 8 * BM;                       // BM

    const int tid  = threadIdx.x;
    const int warp = tid >> 5;
    const int lane = tid & 31;
    const int m0   = blockIdx.x * BM;
    const int Nb   = warp * 16;

    const uint32_t uAh = (uint32_t)__cvta_generic_to_shared(Ah);
    const uint32_t uAl = (uint32_t)__cvta_generic_to_shared(Al);
    const uint32_t uBw = (uint32_t)__cvta_generic_to_shared(Bw)
                         + (uint32_t)warp * (2 * BWB);

    // Per-warp B chunk staging: 4 cp16 per lane covers 16n x 32k x {hi,lo}.
    auto issueB = [&](int kc, int buf) {
        const uint32_t dst = uBw + (uint32_t)buf * BWB;
        #pragma unroll
        for (int t = 0; t < 4; ++t) {
            const int hl  = t >> 1;
            const int idx = lane + 32 * (t & 1);   // 0..63
            const int n   = idx >> 2;              // 0..15 (local row)
            const int pc  = idx & 3;               // 8-elem piece within 32 k
            cp16(dst + (uint32_t)(hl * (BWB / 2) + n * (BS * 2) + pc * 16),
                 (hl ? Wl : Wh) + (Nb + n) * 256 + kc * 32 + pc * 8);
        }
        cpa_commit();
    };

    issueB(0, 0);
    issueB(1, 1);                      // both land during the gather

    if (tid < 128) sBias[tid] = bias[tid];

    // ---------------- gather: warp builds rows warp*R .. +R-1, in pairs ----
    auto storeA = [&](int mL, float4 s4, float2 m01, float2 m23) {
        __nv_bfloat16* rowH = Ah + mL * AS;
        __nv_bfloat16* rowL = Al + mL * AS;
        *(uint2*)(rowH + 4 * lane) =
            make_uint2(pk_bf16(s4.x, s4.y), pk_bf16(s4.z, s4.w));
        *(uint2*)(rowL + 4 * lane) =
            make_uint2(pk_bf16(s4.x - bfrt(s4.x), s4.y - bfrt(s4.y)),
                       pk_bf16(s4.z - bfrt(s4.z), s4.w - bfrt(s4.w)));
        *(uint2*)(rowH + 128 + 4 * lane) =
            make_uint2(pk_bf16(m01.x, m01.y), pk_bf16(m23.x, m23.y));
        *(uint2*)(rowL + 128 + 4 * lane) =
            make_uint2(pk_bf16(m01.x - bfrt(m01.x), m01.y - bfrt(m01.y)),
                       pk_bf16(m23.x - bfrt(m23.x), m23.y - bfrt(m23.y)));
    };

    #pragma unroll 1
    for (int r0 = 0; r0 < R; r0 += 2) {
        const int mLa = warp * R + r0;
        const int mLb = mLa + 1;
        float4 selfA, selfB;
        u64 pa01 = 0, pa23 = 0, qa01 = 0, qa23 = 0;
        u64 pb01 = 0, pb23 = 0, qb01 = 0, qb23 = 0;
        u64 scale;

        if (LAYER == 0) {
            const int jA = m0 + mLa, bA = jA / 11, cA = jA - bA * 11;
            const int jB = m0 + mLb, bB = jB / 11, cB = jB - bB * 11;
            const int sA = (cA == 0) ? __ldg(&nodes[bA])
                                     : __ldg(&nbr1[bA * 10 + cA - 1]);
            const int sB = (cB == 0) ? __ldg(&nodes[bB])
                                     : __ldg(&nbr1[bB * 10 + cB - 1]);
            int idxA = (lane < 25) ? __ldg(&nbr0[(size_t)jA * 25 + lane]) : 0;
            int idxB = (lane < 25) ? __ldg(&nbr0[(size_t)jB * 25 + lane]) : 0;
            selfA = ((const float4*)(src + (size_t)sA * 128))[lane];
            selfB = ((const float4*)(src + (size_t)sB * 128))[lane];
            #pragma unroll
            for (int s = 0; s < 25; ++s) {
                const int na = __shfl_sync(0xffffffffu, idxA, s);
                const int nb = __shfl_sync(0xffffffffu, idxB, s);
                float4 va = ((const float4*)(src + (size_t)na * 128))[lane];
                float4 vb = ((const float4*)(src + (size_t)nb * 128))[lane];
                if (s & 1) {
                    add2(qa01, pack2(va.x, va.y)); add2(qa23, pack2(va.z, va.w));
                    add2(qb01, pack2(vb.x, vb.y)); add2(qb23, pack2(vb.z, vb.w));
                } else {
                    add2(pa01, pack2(va.x, va.y)); add2(pa23, pack2(va.z, va.w));
                    add2(pb01, pack2(vb.x, vb.y)); add2(pb23, pack2(vb.z, vb.w));
                }
            }
            scale = pack2(1.0f / 25.0f, 1.0f / 25.0f);
        } else {
            const float* baseA = src + (size_t)(m0 + mLa) * (11 * 128);
            const float* baseB = src + (size_t)(m0 + mLb) * (11 * 128);
            selfA = ((const float4*)baseA)[lane];
            selfB = ((const float4*)baseB)[lane];
            #pragma unroll
            for (int s = 1; s <= 10; ++s) {
                float4 va = ((const float4*)(baseA + s * 128))[lane];
                float4 vb = ((const float4*)(baseB + s * 128))[lane];
                if (s & 1) {
                    add2(qa01, pack2(va.x, va.y)); add2(qa23, pack2(va.z, va.w));
                    add2(qb01, pack2(vb.x, vb.y)); add2(qb23, pack2(vb.z, vb.w));
                } else {
                    add2(pa01, pack2(va.x, va.y)); add2(pa23, pack2(va.z, va.w));
                    add2(pb01, pack2(vb.x, vb.y)); add2(pb23, pack2(vb.z, vb.w));
                }
            }
            scale = pack2(0.1f, 0.1f);
        }

        add2(pa01, qa01); add2(pa23, qa23);
        add2(pb01, qb01); add2(pb23, qb23);
        storeA(mLa, selfA, unpack2(mul2(pa01, scale)), unpack2(mul2(pa23, scale)));
        storeA(mLb, selfB, unpack2(mul2(pb01, scale)), unpack2(mul2(pb23, scale)));
    }

    __syncthreads();                 // publish A tile (B is warp-private)

    // ---------------- HMMA mainloop: warp-local B pipeline, NO barriers ----
    float acc[MT][2][4];
    #pragma unroll
    for (int mt = 0; mt < MT; ++mt)
        #pragma unroll
        for (int g = 0; g < 2; ++g)
            #pragma unroll
            for (int c = 0; c < 4; ++c) acc[mt][g][c] = 0.f;

    const int li = lane >> 3, lr = lane & 7;

    #pragma unroll 1
    for (int kc = 0; kc < 8; ++kc) {
        // kc<7: chunk kc landed once <=1 group pending (kc+1 still in flight).
        // kc==7: chunk 7 is the ONLY pending group -> must drain fully.
        if (kc == 7) cpa_wait<0>(); else cpa_wait<1>();
        __syncwarp();                // cross-lane visibility within the warp

        const uint32_t bbase = uBw + (uint32_t)(kc & 1) * BWB;

        #pragma unroll
        for (int s = 0; s < 2; ++s) {
            const int k0g = kc * 32 + s * 16;
            uint32_t Ahf[MT][4], Alf[MT][4];
            #pragma unroll
            for (int mt = 0; mt < MT; ++mt) {
                const int row = mt * 16 + (li & 1) * 8 + lr;
                const int col = k0g + (li >> 1) * 8;
                const uint32_t off = (uint32_t)(row * AS + col) * 2;
                ldsm4(Ahf[mt], uAh + off);
                ldsm4(Alf[mt], uAl + off);
            }
            uint32_t Bhf[4], Blf[4];
            {
                const int n  = (li >> 1) * 8 + lr;        // local 0..15
                const int kk = s * 16 + (li & 1) * 8;     // local 0..31
                const uint32_t off = (uint32_t)(n * (BS * 2) + kk * 2);
                ldsm4(Bhf, bbase + off);
                ldsm4(Blf, bbase + (BWB / 2) + off);
            }
            #pragma unroll
            for (int mt = 0; mt < MT; ++mt)
                #pragma unroll
                for (int h = 0; h < 2; ++h) {
                    float* c = acc[mt][h];
                    mma_bf16(c, Ahf[mt], Bhf[2 * h], Bhf[2 * h + 1]);
                    mma_bf16(c, Ahf[mt], Blf[2 * h], Blf[2 * h + 1]);
                    mma_bf16(c, Alf[mt], Bhf[2 * h], Bhf[2 * h + 1]);
                }
        }
        // refill this buffer with chunk kc+2 (mma issued => ldsm reads done)
        if (kc < 6) issueB(kc + 2, kc & 1);
    }

    // ---------------- epilogue: bias + relu + row l2-norm + store ----------
    const int rg = lane >> 2;
    const int lc = (lane & 3) * 2;

    float bb[2][2];
    #pragma unroll
    for (int g = 0; g < 2; ++g) {
        bb[g][0] = sBias[Nb + g * 8 + lc];
        bb[g][1] = sBias[Nb + g * 8 + lc + 1];
    }

    #pragma unroll
    for (int mt = 0; mt < MT; ++mt)
        #pragma unroll
        for (int rh = 0; rh < 2; ++rh) {
            float ss = 0.f;
            #pragma unroll
            for (int g = 0; g < 2; ++g) {
                float v0 = fmaxf(acc[mt][g][2 * rh]     + bb[g][0], 0.f);
                float v1 = fmaxf(acc[mt][g][2 * rh + 1] + bb[g][1], 0.f);
                acc[mt][g][2 * rh]     = v0;
                acc[mt][g][2 * rh + 1] = v1;
                ss += v0 * v0 + v1 * v1;
            }
            ss += __shfl_xor_sync(0xffffffffu, ss, 1);
            ss += __shfl_xor_sync(0xffffffffu, ss, 2);
            if ((lane & 3) == 0)
                red[warp * BM + mt * 16 + rh * 8 + rg] = ss;
        }
    __syncthreads();

    if (tid < BM) {
        float t = 0.f;
        #pragma unroll
        for (int n = 0; n < 8; ++n) t += red[n * BM + tid];
        sInv[tid] = 1.0f / fmaxf(sqrtf(t), 1e-12f);
    }
    __syncthreads();

    #pragma unroll
    for (int mt = 0; mt < MT; ++mt)
        #pragma unroll
        for (int rh = 0; rh < 2; ++rh) {
            const int row = mt * 16 + rh * 8 + rg;
            const float inv = sInv[row];
            float* orow = out + (size_t)(m0 + row) * 128 + Nb + lc;
            #pragma unroll
            for (int g = 0; g < 2; ++g)
                *(float2*)(orow + g * 8) =
                    make_float2(acc[mt][g][2 * rh] * inv,
                                acc[mt][g][2 * rh + 1] * inv);
        }
}

extern "C" void kernel_launch(void* const* d_in, const int* in_sizes, int n_in,
                              void* d_out, int out_size)
{
    (void)in_sizes; (void)n_in; (void)out_size;

    const float* features = (const float*)d_in[0];
    const float* W0       = (const float*)d_in[1];
    const float* b0       = (const float*)d_in[2];
    const float* W1       = (const float*)d_in[3];
    const float* b1       = (const float*)d_in[4];
    const int*   nodes    = (const int*)d_in[5];
    const int*   nbr1     = (const int*)d_in[6];
    const int*   nbr0     = (const int*)d_in[7];
    float*       out      = (float*)d_out;

    // smem bytes: 2*BM*AS*2 + 8*2*BWB + 512 + 8*BM*4 + BM*4
    const int SMEM0 = 2 * 32 * AS * 2 + 8 * 2 * BWB + 512 + 8 * 32 * 4 + 32 * 4;
    const int SMEM1 = 2 * 16 * AS * 2 + 8 * 2 * BWB + 512 + 8 * 16 * 4 + 16 * 4;

    cudaFuncSetAttribute(sage_hmma<0, 32>,
                         cudaFuncAttributeMaxDynamicSharedMemorySize, SMEM0);
    cudaFuncSetAttribute(sage_hmma<0, 32>,
                         cudaFuncAttributePreferredSharedMemoryCarveout, 100);
    cudaFuncSetAttribute(sage_hmma<1, 16>,
                         cudaFuncAttributeMaxDynamicSharedMemorySize, SMEM1);
    cudaFuncSetAttribute(sage_hmma<1, 16>,
                         cudaFuncAttributePreferredSharedMemoryCarveout, 100);

    float *h1; __nv_bfloat16 *w0h, *w0l, *w1h, *w1l;
    cudaGetSymbolAddress((void**)&h1,  g_h1);
    cudaGetSymbolAddress((void**)&w0h, g_W0h);
    cudaGetSymbolAddress((void**)&w0l, g_W0l);
    cudaGetSymbolAddress((void**)&w1h, g_W1h);
    cudaGetSymbolAddress((void**)&w1l, g_W1l);

    prep_w<<<32, 256>>>(W0, W1);
    sage_hmma<0, 32><<<L1_ROWS / 32, THREADS, SMEM0>>>(
        features, nodes, nbr1, nbr0, w0h, w0l, b0, h1);
    sage_hmma<1, 16><<<B_TARGETS / 16, THREADS, SMEM1>>>(
        h1, nullptr, nullptr, nullptr, w1h, w1l, b1, out);
}

// round 16
// speedup vs baseline: 1.2307x; 1.0314x over previous
#include <cuda_runtime.h>
#include <cuda_bf16.h>
#include <cstdint>
#include <cstddef>

#define THREADS   256
#define AS        264    // A row stride (bf16): 528B rows, ldmatrix conflict-free
#define BS        40     // B row stride (bf16): 80B rows, ldmatrix conflict-free
#define BWB       2560   // bytes per warp B buffer (2 hl * 16 n * 80B)
#define B_TARGETS 4096
#define L1_ROWS   (B_TARGETS * 11)   // 45056

__device__ __align__(256) float         g_h1[L1_ROWS * 128];
__device__ __align__(256) __nv_bfloat16 g_W0h[128 * 256];
__device__ __align__(256) __nv_bfloat16 g_W0l[128 * 256];
__device__ __align__(256) __nv_bfloat16 g_W1h[128 * 256];
__device__ __align__(256) __nv_bfloat16 g_W1l[128 * 256];

typedef unsigned long long u64;

__device__ __forceinline__ float bfrt(float x) {
    float r;
    asm("{\n\t.reg .b16 t;\n\tcvt.rn.bf16.f32 t, %1;\n\tcvt.f32.bf16 %0, t;\n\t}"
        : "=f"(r) : "f"(x));
    return r;
}
__device__ __forceinline__ uint32_t pk_bf16(float x, float y) {
    uint32_t r;
    asm("{\n\t.reg .b16 l, h;\n\tcvt.rn.bf16.f32 l, %1;\n\tcvt.rn.bf16.f32 h, %2;\n\t"
        "mov.b32 %0, {l, h};\n\t}" : "=r"(r) : "f"(x), "f"(y));
    return r;
}
__device__ __forceinline__ void add2(u64& d, u64 a) {
    asm("add.rn.f32x2 %0, %1, %0;" : "+l"(d) : "l"(a));
}
__device__ __forceinline__ u64 pack2(float lo, float hi) {
    u64 r; asm("mov.b64 %0, {%1, %2};" : "=l"(r) : "f"(lo), "f"(hi)); return r;
}
__device__ __forceinline__ float2 unpack2(u64 v) {
    float2 r; asm("mov.b64 {%0, %1}, %2;" : "=f"(r.x), "=f"(r.y) : "l"(v)); return r;
}
__device__ __forceinline__ u64 mul2(u64 a, u64 b) {
    u64 r; asm("mul.rn.f32x2 %0, %1, %2;" : "=l"(r) : "l"(a), "l"(b)); return r;
}
__device__ __forceinline__ void cp16(uint32_t dst, const void* src) {
    asm volatile("cp.async.cg.shared.global [%0], [%1], 16;" :: "r"(dst), "l"(src));
}
__device__ __forceinline__ void cpa_commit() {
    asm volatile("cp.async.commit_group;");
}
template <int N>
__device__ __forceinline__ void cpa_wait() {
    asm volatile("cp.async.wait_group %0;" :: "n"(N));
}
__device__ __forceinline__ void ldsm4(uint32_t* r, uint32_t addr) {
    asm volatile("ldmatrix.sync.aligned.m8n8.x4.shared.b16 {%0,%1,%2,%3}, [%4];"
                 : "=r"(r[0]), "=r"(r[1]), "=r"(r[2]), "=r"(r[3]) : "r"(addr));
}
__device__ __forceinline__ void mma_bf16(float* c, const uint32_t* a,
                                         uint32_t b0, uint32_t b1) {
    asm volatile("mma.sync.aligned.m16n8k16.row.col.f32.bf16.bf16.f32 "
                 "{%0,%1,%2,%3}, {%4,%5,%6,%7}, {%8,%9}, {%0,%1,%2,%3};"
                 : "+f"(c[0]), "+f"(c[1]), "+f"(c[2]), "+f"(c[3])
                 : "r"(a[0]), "r"(a[1]), "r"(a[2]), "r"(a[3]), "r"(b0), "r"(b1));
}

// Pre-split W0/W1 into bf16 hi/lo. 64 blocks x 128 threads, 1 float4 each.
__global__ void prep_w(const float* __restrict__ W0, const float* __restrict__ W1) {
    const int i = blockIdx.x * 128 + threadIdx.x;      // 0..8191 float4 groups
    const float4 a = ((const float4*)W0)[i];
    const float4 b = ((const float4*)W1)[i];
    *(uint2*)(g_W0h + 4 * i) =
        make_uint2(pk_bf16(a.x, a.y), pk_bf16(a.z, a.w));
    *(uint2*)(g_W0l + 4 * i) =
        make_uint2(pk_bf16(a.x - bfrt(a.x), a.y - bfrt(a.y)),
                   pk_bf16(a.z - bfrt(a.z), a.w - bfrt(a.w)));
    *(uint2*)(g_W1h + 4 * i) =
        make_uint2(pk_bf16(b.x, b.y), pk_bf16(b.z, b.w));
    *(uint2*)(g_W1l + 4 * i) =
        make_uint2(pk_bf16(b.x - bfrt(b.x), b.y - bfrt(b.y)),
                   pk_bf16(b.z - bfrt(b.z), b.w - bfrt(b.w)));
}

// Fused tile: register-LDG gather (quad-row interleave, 4 independent load
// streams per warp) -> bf16 hi/lo A -> HMMA (3-product bf16 split, fp32
// accum) -> bias+relu+row-l2norm -> out.
// 8 warps each own 16 output cols. B: per-warp private cp.async double buffer
// (warp-local wait_group+syncwarp, NO block barriers in the mainloop).
// LAYER 0: rows = level-1 nodes (self feat || mean of 25 nbr feats).
// LAYER 1: rows = targets       (h1[b,0]   || mean of h1[b,1..10]).
template <int LAYER, int BM>
__global__ __launch_bounds__(THREADS, 3)
void sage_hmma(const float* __restrict__ src,
               const int*   __restrict__ nodes,
               const int*   __restrict__ nbr1,
               const int*   __restrict__ nbr0,
               const __nv_bfloat16* __restrict__ Wh,   // [128 n][256 k]
               const __nv_bfloat16* __restrict__ Wl,
               const float* __restrict__ bias,
               float*       __restrict__ out)          // [rows][128]
{
    constexpr int MT = BM / 16;        // 16-row tiles per block
    constexpr int R  = BM / 8;         // gather rows per warp

    extern __shared__ char sm[];
    __nv_bfloat16* Ah  = (__nv_bfloat16*)sm;           // BM*AS
    __nv_bfloat16* Al  = Ah + BM * AS;                 // BM*AS
    char* Bw = (char*)(Al + BM * AS);                  // 8 warps * 2 bufs * BWB
    float* sBias = (float*)(Bw + 8 * 2 * BWB);         // 128
    float* red   = sBias + 128;                        // [8][BM]
    float* sInv  = red + 8 * BM;                       // BM

    const int tid  = threadIdx.x;
    const int warp = tid >> 5;
    const int lane = tid & 31;
    const int m0   = blockIdx.x * BM;
    const int Nb   = warp * 16;

    const uint32_t uAh = (uint32_t)__cvta_generic_to_shared(Ah);
    const uint32_t uAl = (uint32_t)__cvta_generic_to_shared(Al);
    const uint32_t uBw = (uint32_t)__cvta_generic_to_shared(Bw)
                         + (uint32_t)warp * (2 * BWB);

    // Per-warp B chunk staging: 4 cp16 per lane covers 16n x 32k x {hi,lo}.
    auto issueB = [&](int kc, int buf) {
        const uint32_t dst = uBw + (uint32_t)buf * BWB;
        #pragma unroll
        for (int t = 0; t < 4; ++t) {
            const int hl  = t >> 1;
            const int idx = lane + 32 * (t & 1);   // 0..63
            const int n   = idx >> 2;              // 0..15 (local row)
            const int pc  = idx & 3;               // 8-elem piece within 32 k
            cp16(dst + (uint32_t)(hl * (BWB / 2) + n * (BS * 2) + pc * 16),
                 (hl ? Wl : Wh) + (Nb + n) * 256 + kc * 32 + pc * 8);
        }
        cpa_commit();
    };

    issueB(0, 0);
    issueB(1, 1);                      // both land during the gather

    if (tid < 128) sBias[tid] = bias[tid];

    // ---------------- gather -----------------------------------------------
    auto storeA = [&](int mL, float4 s4, float2 m01, float2 m23) {
        __nv_bfloat16* rowH = Ah + mL * AS;
        __nv_bfloat16* rowL = Al + mL * AS;
        *(uint2*)(rowH + 4 * lane) =
            make_uint2(pk_bf16(s4.x, s4.y), pk_bf16(s4.z, s4.w));
        *(uint2*)(rowL + 4 * lane) =
            make_uint2(pk_bf16(s4.x - bfrt(s4.x), s4.y - bfrt(s4.y)),
                       pk_bf16(s4.z - bfrt(s4.z), s4.w - bfrt(s4.w)));
        *(uint2*)(rowH + 128 + 4 * lane) =
            make_uint2(pk_bf16(m01.x, m01.y), pk_bf16(m23.x, m23.y));
        *(uint2*)(rowL + 128 + 4 * lane) =
            make_uint2(pk_bf16(m01.x - bfrt(m01.x), m01.y - bfrt(m01.y)),
                       pk_bf16(m23.x - bfrt(m23.x), m23.y - bfrt(m23.y)));
    };

    if constexpr (LAYER == 0) {
        // quad-row interleave: 4 independent index regs + accumulation chains
        static_assert(R == 4, "layer0 expects BM=32");
        int idx[4];
        float4 self[4];
        u64 a01[4], a23[4];
        #pragma unroll
        for (int r = 0; r < 4; ++r) {
            const int j = m0 + warp * 4 + r, b = j / 11, c = j - b * 11;
            const int sidx = (c == 0) ? __ldg(&nodes[b])
                                      : __ldg(&nbr1[b * 10 + c - 1]);
            idx[r]  = (lane < 25) ? __ldg(&nbr0[(size_t)j * 25 + lane]) : 0;
            self[r] = ((const float4*)(src + (size_t)sidx * 128))[lane];
            a01[r] = 0; a23[r] = 0;
        }
        #pragma unroll
        for (int s = 0; s < 25; ++s) {
            #pragma unroll
            for (int r = 0; r < 4; ++r) {
                const int ni = __shfl_sync(0xffffffffu, idx[r], s);
                const float4 v = ((const float4*)(src + (size_t)ni * 128))[lane];
                add2(a01[r], pack2(v.x, v.y));
                add2(a23[r], pack2(v.z, v.w));
            }
        }
        const u64 sc = pack2(1.0f / 25.0f, 1.0f / 25.0f);
        #pragma unroll
        for (int r = 0; r < 4; ++r)
            storeA(warp * 4 + r, self[r],
                   unpack2(mul2(a01[r], sc)), unpack2(mul2(a23[r], sc)));
    } else {
        // layer 1: R rows in pairs from contiguous g_h1 (L2-resident)
        #pragma unroll 1
        for (int r0 = 0; r0 < R; r0 += 2) {
            const int mLa = warp * R + r0;
            const int mLb = mLa + 1;
            const float* baseA = src + (size_t)(m0 + mLa) * (11 * 128);
            const float* baseB = src + (size_t)(m0 + mLb) * (11 * 128);
            const float4 selfA = ((const float4*)baseA)[lane];
            const float4 selfB = ((const float4*)baseB)[lane];
            u64 pa01 = 0, pa23 = 0, qa01 = 0, qa23 = 0;
            u64 pb01 = 0, pb23 = 0, qb01 = 0, qb23 = 0;
            #pragma unroll
            for (int s = 1; s <= 10; ++s) {
                float4 va = ((const float4*)(baseA + s * 128))[lane];
                float4 vb = ((const float4*)(baseB + s * 128))[lane];
                if (s & 1) {
                    add2(qa01, pack2(va.x, va.y)); add2(qa23, pack2(va.z, va.w));
                    add2(qb01, pack2(vb.x, vb.y)); add2(qb23, pack2(vb.z, vb.w));
                } else {
                    add2(pa01, pack2(va.x, va.y)); add2(pa23, pack2(va.z, va.w));
                    add2(pb01, pack2(vb.x, vb.y)); add2(pb23, pack2(vb.z, vb.w));
                }
            }
            const u64 scale = pack2(0.1f, 0.1f);
            add2(pa01, qa01); add2(pa23, qa23);
            add2(pb01, qb01); add2(pb23, qb23);
            storeA(mLa, selfA, unpack2(mul2(pa01, scale)), unpack2(mul2(pa23, scale)));
            storeA(mLb, selfB, unpack2(mul2(pb01, scale)), unpack2(mul2(pb23, scale)));
        }
    }

    __syncthreads();                 // publish A tile (B is warp-private)

    // ---------------- HMMA mainloop: warp-local B pipeline, NO barriers ----
    float acc[MT][2][4];
    #pragma unroll
    for (int mt = 0; mt < MT; ++mt)
        #pragma unroll
        for (int g = 0; g < 2; ++g)
            #pragma unroll
            for (int c = 0; c < 4; ++c) acc[mt][g][c] = 0.f;

    const int li = lane >> 3, lr = lane & 7;

    #pragma unroll 1
    for (int kc = 0; kc < 8; ++kc) {
        // kc<7: chunk kc landed once <=1 group pending (kc+1 still in flight).
        // kc==7: chunk 7 is the ONLY pending group -> must drain fully.
        if (kc == 7) cpa_wait<0>(); else cpa_wait<1>();
        __syncwarp();                // cross-lane visibility within the warp

        const uint32_t bbase = uBw + (uint32_t)(kc & 1) * BWB;

        #pragma unroll
        for (int s = 0; s < 2; ++s) {
            const int k0g = kc * 32 + s * 16;
            uint32_t Ahf[MT][4], Alf[MT][4];
            #pragma unroll
            for (int mt = 0; mt < MT; ++mt) {
                const int row = mt * 16 + (li & 1) * 8 + lr;
                const int col = k0g + (li >> 1) * 8;
                const uint32_t off = (uint32_t)(row * AS + col) * 2;
                ldsm4(Ahf[mt], uAh + off);
                ldsm4(Alf[mt], uAl + off);
            }
            uint32_t Bhf[4], Blf[4];
            {
                const int n  = (li >> 1) * 8 + lr;        // local 0..15
                const int kk = s * 16 + (li & 1) * 8;     // local 0..31
                const uint32_t off = (uint32_t)(n * (BS * 2) + kk * 2);
                ldsm4(Bhf, bbase + off);
                ldsm4(Blf, bbase + (BWB / 2) + off);
            }
            #pragma unroll
            for (int mt = 0; mt < MT; ++mt)
                #pragma unroll
                for (int h = 0; h < 2; ++h) {
                    float* c = acc[mt][h];
                    mma_bf16(c, Ahf[mt], Bhf[2 * h], Bhf[2 * h + 1]);
                    mma_bf16(c, Ahf[mt], Blf[2 * h], Blf[2 * h + 1]);
                    mma_bf16(c, Alf[mt], Bhf[2 * h], Bhf[2 * h + 1]);
                }
        }
        // refill this buffer with chunk kc+2 (mma issued => ldsm reads done)
        if (kc < 6) issueB(kc + 2, kc & 1);
    }

    // ---------------- epilogue: bias + relu + row l2-norm + store ----------
    const int rg = lane >> 2;
    const int lc = (lane & 3) * 2;

    float bb[2][2];
    #pragma unroll
    for (int g = 0; g < 2; ++g) {
        bb[g][0] = sBias[Nb + g * 8 + lc];
        bb[g][1] = sBias[Nb + g * 8 + lc + 1];
    }

    #pragma unroll
    for (int mt = 0; mt < MT; ++mt)
        #pragma unroll
        for (int rh = 0; rh < 2; ++rh) {
            float ss = 0.f;
            #pragma unroll
            for (int g = 0; g < 2; ++g) {
                float v0 = fmaxf(acc[mt][g][2 * rh]     + bb[g][0], 0.f);
                float v1 = fmaxf(acc[mt][g][2 * rh + 1] + bb[g][1], 0.f);
                acc[mt][g][2 * rh]     = v0;
                acc[mt][g][2 * rh + 1] = v1;
                ss += v0 * v0 + v1 * v1;
            }
            ss += __shfl_xor_sync(0xffffffffu, ss, 1);
            ss += __shfl_xor_sync(0xffffffffu, ss, 2);
            if ((lane & 3) == 0)
                red[warp * BM + mt * 16 + rh * 8 + rg] = ss;
        }
    __syncthreads();

    if (tid < BM) {
        float t = 0.f;
        #pragma unroll
        for (int n = 0; n < 8; ++n) t += red[n * BM + tid];
        sInv[tid] = 1.0f / fmaxf(sqrtf(t), 1e-12f);
    }
    __syncthreads();

    #pragma unroll
    for (int mt = 0; mt < MT; ++mt)
        #pragma unroll
        for (int rh = 0; rh < 2; ++rh) {
            const int row = mt * 16 + rh * 8 + rg;
            const float inv = sInv[row];
            float* orow = out + (size_t)(m0 + row) * 128 + Nb + lc;
            #pragma unroll
            for (int g = 0; g < 2; ++g)
                *(float2*)(orow + g * 8) =
                    make_float2(acc[mt][g][2 * rh] * inv,
                                acc[mt][g][2 * rh + 1] * inv);
        }
}

extern "C" void kernel_launch(void* const* d_in, const int* in_sizes, int n_in,
                              void* d_out, int out_size)
{
    (void)in_sizes; (void)n_in; (void)out_size;

    const float* features = (const float*)d_in[0];
    const float* W0       = (const float*)d_in[1];
    const float* b0       = (const float*)d_in[2];
    const float* W1       = (const float*)d_in[3];
    const float* b1       = (const float*)d_in[4];
    const int*   nodes    = (const int*)d_in[5];
    const int*   nbr1     = (const int*)d_in[6];
    const int*   nbr0     = (const int*)d_in[7];
    float*       out      = (float*)d_out;

    // smem bytes: 2*BM*AS*2 + 8*2*BWB + 512 + 8*BM*4 + BM*4
    const int SMEM0 = 2 * 32 * AS * 2 + 8 * 2 * BWB + 512 + 8 * 32 * 4 + 32 * 4;
    const int SMEM1 = 2 * 16 * AS * 2 + 8 * 2 * BWB + 512 + 8 * 16 * 4 + 16 * 4;

    cudaFuncSetAttribute(sage_hmma<0, 32>,
                         cudaFuncAttributeMaxDynamicSharedMemorySize, SMEM0);
    cudaFuncSetAttribute(sage_hmma<0, 32>,
                         cudaFuncAttributePreferredSharedMemoryCarveout, 100);
    cudaFuncSetAttribute(sage_hmma<1, 16>,
                         cudaFuncAttributeMaxDynamicSharedMemorySize, SMEM1);
    cudaFuncSetAttribute(sage_hmma<1, 16>,
                         cudaFuncAttributePreferredSharedMemoryCarveout, 100);

    float *h1; __nv_bfloat16 *w0h, *w0l, *w1h, *w1l;
    cudaGetSymbolAddress((void**)&h1,  g_h1);
    cudaGetSymbolAddress((void**)&w0h, g_W0h);
    cudaGetSymbolAddress((void**)&w0l, g_W0l);
    cudaGetSymbolAddress((void**)&w1h, g_W1h);
    cudaGetSymbolAddress((void**)&w1l, g_W1l);

    prep_w<<<64, 128>>>(W0, W1);
    sage_hmma<0, 32><<<L1_ROWS / 32, THREADS, SMEM0>>>(
        features, nodes, nbr1, nbr0, w0h, w0l, b0, h1);
    sage_hmma<1, 16><<<B_TARGETS / 16, THREADS, SMEM1>>>(
        h1, nullptr, nullptr, nullptr, w1h, w1l, b1, out);
}

// round 17
// speedup vs baseline: 1.2310x; 1.0002x over previous
#include <cuda_runtime.h>
#include <cuda_bf16.h>
#include <cstdint>
#include <cstddef>

#define THREADS   256
#define AS        264    // A row stride (bf16): 528B rows, ldmatrix conflict-free
#define BS        40     // B row stride (bf16): 80B rows, ldmatrix conflict-free
#define BWB       2560   // bytes per warp B buffer (2 hl * 16 n * 80B)
#define B_TARGETS 4096
#define L1_ROWS   (B_TARGETS * 11)   // 45056

__device__ __align__(256) float         g_h1[L1_ROWS * 128];
__device__ __align__(256) __nv_bfloat16 g_W0h[128 * 256];
__device__ __align__(256) __nv_bfloat16 g_W0l[128 * 256];
__device__ __align__(256) __nv_bfloat16 g_W1h[128 * 256];
__device__ __align__(256) __nv_bfloat16 g_W1l[128 * 256];

typedef unsigned long long u64;

__device__ __forceinline__ float bfrt(float x) {
    float r;
    asm("{\n\t.reg .b16 t;\n\tcvt.rn.bf16.f32 t, %1;\n\tcvt.f32.bf16 %0, t;\n\t}"
        : "=f"(r) : "f"(x));
    return r;
}
__device__ __forceinline__ uint32_t pk_bf16(float x, float y) {
    uint32_t r;
    asm("{\n\t.reg .b16 l, h;\n\tcvt.rn.bf16.f32 l, %1;\n\tcvt.rn.bf16.f32 h, %2;\n\t"
        "mov.b32 %0, {l, h};\n\t}" : "=r"(r) : "f"(x), "f"(y));
    return r;
}
__device__ __forceinline__ void add2(u64& d, u64 a) {
    asm("add.rn.f32x2 %0, %1, %0;" : "+l"(d) : "l"(a));
}
__device__ __forceinline__ u64 pack2(float lo, float hi) {
    u64 r; asm("mov.b64 %0, {%1, %2};" : "=l"(r) : "f"(lo), "f"(hi)); return r;
}
__device__ __forceinline__ float2 unpack2(u64 v) {
    float2 r; asm("mov.b64 {%0, %1}, %2;" : "=f"(r.x), "=f"(r.y) : "l"(v)); return r;
}
__device__ __forceinline__ u64 mul2(u64 a, u64 b) {
    u64 r; asm("mul.rn.f32x2 %0, %1, %2;" : "=l"(r) : "l"(a), "l"(b)); return r;
}
__device__ __forceinline__ void cp16(uint32_t dst, const void* src) {
    asm volatile("cp.async.cg.shared.global [%0], [%1], 16;" :: "r"(dst), "l"(src));
}
__device__ __forceinline__ void cpa_commit() {
    asm volatile("cp.async.commit_group;");
}
template <int N>
__device__ __forceinline__ void cpa_wait() {
    asm volatile("cp.async.wait_group %0;" :: "n"(N));
}
__device__ __forceinline__ void ldsm4(uint32_t* r, uint32_t addr) {
    asm volatile("ldmatrix.sync.aligned.m8n8.x4.shared.b16 {%0,%1,%2,%3}, [%4];"
                 : "=r"(r[0]), "=r"(r[1]), "=r"(r[2]), "=r"(r[3]) : "r"(addr));
}
__device__ __forceinline__ void mma_bf16(float* c, const uint32_t* a,
                                         uint32_t b0, uint32_t b1) {
    asm volatile("mma.sync.aligned.m16n8k16.row.col.f32.bf16.bf16.f32 "
                 "{%0,%1,%2,%3}, {%4,%5,%6,%7}, {%8,%9}, {%0,%1,%2,%3};"
                 : "+f"(c[0]), "+f"(c[1]), "+f"(c[2]), "+f"(c[3])
                 : "r"(a[0]), "r"(a[1]), "r"(a[2]), "r"(a[3]), "r"(b0), "r"(b1));
}

// Pre-split W0/W1 into bf16 hi/lo. 16384 threads, 1 float4 of 1 matrix each.
__global__ void prep_w(const float* __restrict__ W0, const float* __restrict__ W1) {
    const int g = blockIdx.x * 128 + threadIdx.x;      // 0..16383
    const int i = g & 8191;                            // float4 group
    if (g < 8192) {
        const float4 a = ((const float4*)W0)[i];
        *(uint2*)(g_W0h + 4 * i) =
            make_uint2(pk_bf16(a.x, a.y), pk_bf16(a.z, a.w));
        *(uint2*)(g_W0l + 4 * i) =
            make_uint2(pk_bf16(a.x - bfrt(a.x), a.y - bfrt(a.y)),
                       pk_bf16(a.z - bfrt(a.z), a.w - bfrt(a.w)));
    } else {
        const float4 b = ((const float4*)W1)[i];
        *(uint2*)(g_W1h + 4 * i) =
            make_uint2(pk_bf16(b.x, b.y), pk_bf16(b.z, b.w));
        *(uint2*)(g_W1l + 4 * i) =
            make_uint2(pk_bf16(b.x - bfrt(b.x), b.y - bfrt(b.y)),
                       pk_bf16(b.z - bfrt(b.z), b.w - bfrt(b.w)));
    }
}

// Fused tile: register-LDG gather (quad-row interleave) -> bf16 hi/lo A ->
// HMMA (3-product bf16 split, fp32 accum) -> bias+relu+row-l2norm -> out.
// 8 warps each own 16 output cols. B: per-warp private cp.async buffer ring,
// NBUF buffers (warp-local wait_group+syncwarp, NO block barriers in loop).
// LAYER 0: NBUF=1 -> 55.9 KB smem -> occupancy 4 (gather overlap).
// LAYER 1: NBUF=2 -> deeper pipeline, occupancy 3 (short critical path).
template <int LAYER, int BM, int NBUF>
__global__ __launch_bounds__(THREADS, (LAYER == 0) ? 4 : 3)
void sage_hmma(const float* __restrict__ src,
               const int*   __restrict__ nodes,
               const int*   __restrict__ nbr1,
               const int*   __restrict__ nbr0,
               const __nv_bfloat16* __restrict__ Wh,   // [128 n][256 k]
               const __nv_bfloat16* __restrict__ Wl,
               const float* __restrict__ bias,
               float*       __restrict__ out)          // [rows][128]
{
    constexpr int MT = BM / 16;        // 16-row tiles per block
    constexpr int R  = BM / 8;         // gather rows per warp

    extern __shared__ char sm[];
    __nv_bfloat16* Ah  = (__nv_bfloat16*)sm;           // BM*AS
    __nv_bfloat16* Al  = Ah + BM * AS;                 // BM*AS
    char* Bw = (char*)(Al + BM * AS);                  // 8 warps * NBUF * BWB
    float* sBias = (float*)(Bw + 8 * NBUF * BWB);      // 128
    float* red   = sBias + 128;                        // [8][BM]
    float* sInv  = red + 8 * BM;                       // BM

    const int tid  = threadIdx.x;
    const int warp = tid >> 5;
    const int lane = tid & 31;
    const int m0   = blockIdx.x * BM;
    const int Nb   = warp * 16;

    const uint32_t uAh = (uint32_t)__cvta_generic_to_shared(Ah);
    const uint32_t uAl = (uint32_t)__cvta_generic_to_shared(Al);
    const uint32_t uBw = (uint32_t)__cvta_generic_to_shared(Bw)
                         + (uint32_t)warp * (NBUF * BWB);

    // Per-warp B chunk staging: 4 cp16 per lane covers 16n x 32k x {hi,lo}.
    auto issueB = [&](int kc, int buf) {
        const uint32_t dst = uBw + (uint32_t)buf * BWB;
        #pragma unroll
        for (int t = 0; t < 4; ++t) {
            const int hl  = t >> 1;
            const int idx = lane + 32 * (t & 1);   // 0..63
            const int n   = idx >> 2;              // 0..15 (local row)
            const int pc  = idx & 3;               // 8-elem piece within 32 k
            cp16(dst + (uint32_t)(hl * (BWB / 2) + n * (BS * 2) + pc * 16),
                 (hl ? Wl : Wh) + (Nb + n) * 256 + kc * 32 + pc * 8);
        }
        cpa_commit();
    };

    issueB(0, 0);                          // lands during the gather
    if constexpr (NBUF == 2) issueB(1, 1);

    if (tid < 128) sBias[tid] = bias[tid];

    // ---------------- gather -----------------------------------------------
    auto storeA = [&](int mL, float4 s4, float2 m01, float2 m23) {
        __nv_bfloat16* rowH = Ah + mL * AS;
        __nv_bfloat16* rowL = Al + mL * AS;
        *(uint2*)(rowH + 4 * lane) =
            make_uint2(pk_bf16(s4.x, s4.y), pk_bf16(s4.z, s4.w));
        *(uint2*)(rowL + 4 * lane) =
            make_uint2(pk_bf16(s4.x - bfrt(s4.x), s4.y - bfrt(s4.y)),
                       pk_bf16(s4.z - bfrt(s4.z), s4.w - bfrt(s4.w)));
        *(uint2*)(rowH + 128 + 4 * lane) =
            make_uint2(pk_bf16(m01.x, m01.y), pk_bf16(m23.x, m23.y));
        *(uint2*)(rowL + 128 + 4 * lane) =
            make_uint2(pk_bf16(m01.x - bfrt(m01.x), m01.y - bfrt(m01.y)),
                       pk_bf16(m23.x - bfrt(m23.x), m23.y - bfrt(m23.y)));
    };

    if constexpr (LAYER == 0) {
        // quad-row interleave: 4 independent index regs + accumulation chains
        static_assert(R == 4, "layer0 expects BM=32");
        int idx[4];
        float4 self[4];
        u64 a01[4], a23[4];
        #pragma unroll
        for (int r = 0; r < 4; ++r) {
            const int j = m0 + warp * 4 + r, b = j / 11, c = j - b * 11;
            const int sidx = (c == 0) ? __ldg(&nodes[b])
                                      : __ldg(&nbr1[b * 10 + c - 1]);
            idx[r]  = (lane < 25) ? __ldg(&nbr0[(size_t)j * 25 + lane]) : 0;
            self[r] = ((const float4*)(src + (size_t)sidx * 128))[lane];
            a01[r] = 0; a23[r] = 0;
        }
        #pragma unroll
        for (int s = 0; s < 25; ++s) {
            #pragma unroll
            for (int r = 0; r < 4; ++r) {
                const int ni = __shfl_sync(0xffffffffu, idx[r], s);
                const float4 v = ((const float4*)(src + (size_t)ni * 128))[lane];
                add2(a01[r], pack2(v.x, v.y));
                add2(a23[r], pack2(v.z, v.w));
            }
        }
        const u64 sc = pack2(1.0f / 25.0f, 1.0f / 25.0f);
        #pragma unroll
        for (int r = 0; r < 4; ++r)
            storeA(warp * 4 + r, self[r],
                   unpack2(mul2(a01[r], sc)), unpack2(mul2(a23[r], sc)));
    } else {
        // layer 1: R rows in pairs from contiguous g_h1 (L2-resident)
        #pragma unroll 1
        for (int r0 = 0; r0 < R; r0 += 2) {
            const int mLa = warp * R + r0;
            const int mLb = mLa + 1;
            const float* baseA = src + (size_t)(m0 + mLa) * (11 * 128);
            const float* baseB = src + (size_t)(m0 + mLb) * (11 * 128);
            const float4 selfA = ((const float4*)baseA)[lane];
            const float4 selfB = ((const float4*)baseB)[lane];
            u64 pa01 = 0, pa23 = 0, qa01 = 0, qa23 = 0;
            u64 pb01 = 0, pb23 = 0, qb01 = 0, qb23 = 0;
            #pragma unroll
            for (int s = 1; s <= 10; ++s) {
                float4 va = ((const float4*)(baseA + s * 128))[lane];
                float4 vb = ((const float4*)(baseB + s * 128))[lane];
                if (s & 1) {
                    add2(qa01, pack2(va.x, va.y)); add2(qa23, pack2(va.z, va.w));
                    add2(qb01, pack2(vb.x, vb.y)); add2(qb23, pack2(vb.z, vb.w));
                } else {
                    add2(pa01, pack2(va.x, va.y)); add2(pa23, pack2(va.z, va.w));
                    add2(pb01, pack2(vb.x, vb.y)); add2(pb23, pack2(vb.z, vb.w));
                }
            }
            const u64 scale = pack2(0.1f, 0.1f);
            add2(pa01, qa01); add2(pa23, qa23);
            add2(pb01, qb01); add2(pb23, qb23);
            storeA(mLa, selfA, unpack2(mul2(pa01, scale)), unpack2(mul2(pa23, scale)));
            storeA(mLb, selfB, unpack2(mul2(pb01, scale)), unpack2(mul2(pb23, scale)));
        }
    }

    __syncthreads();                 // publish A tile (B is warp-private)

    // ---------------- HMMA mainloop: warp-local B pipeline, NO barriers ----
    float acc[MT][2][4];
    #pragma unroll
    for (int mt = 0; mt < MT; ++mt)
        #pragma unroll
        for (int g = 0; g < 2; ++g)
            #pragma unroll
            for (int c = 0; c < 4; ++c) acc[mt][g][c] = 0.f;

    const int li = lane >> 3, lr = lane & 7;

    #pragma unroll 1
    for (int kc = 0; kc < 8; ++kc) {
        if constexpr (NBUF == 2) {
            // kc<7: chunk kc landed once <=1 group pending; kc==7: drain all.
            if (kc == 7) cpa_wait<0>(); else cpa_wait<1>();
        } else {
            cpa_wait<0>();           // single buffer: drain before reading
        }
        __syncwarp();                // cross-lane visibility within the warp

        const uint32_t bbase =
            uBw + (uint32_t)((NBUF == 2) ? (kc & 1) : 0) * BWB;

        #pragma unroll
        for (int s = 0; s < 2; ++s) {
            const int k0g = kc * 32 + s * 16;
            uint32_t Ahf[MT][4], Alf[MT][4];
            #pragma unroll
            for (int mt = 0; mt < MT; ++mt) {
                const int row = mt * 16 + (li & 1) * 8 + lr;
                const int col = k0g + (li >> 1) * 8;
                const uint32_t off = (uint32_t)(row * AS + col) * 2;
                ldsm4(Ahf[mt], uAh + off);
                ldsm4(Alf[mt], uAl + off);
            }
            uint32_t Bhf[4], Blf[4];
            {
                const int n  = (li >> 1) * 8 + lr;        // local 0..15
                const int kk = s * 16 + (li & 1) * 8;     // local 0..31
                const uint32_t off = (uint32_t)(n * (BS * 2) + kk * 2);
                ldsm4(Bhf, bbase + off);
                ldsm4(Blf, bbase + (BWB / 2) + off);
            }
            #pragma unroll
            for (int mt = 0; mt < MT; ++mt)
                #pragma unroll
                for (int h = 0; h < 2; ++h) {
                    float* c = acc[mt][h];
                    mma_bf16(c, Ahf[mt], Bhf[2 * h], Bhf[2 * h + 1]);
                    mma_bf16(c, Ahf[mt], Blf[2 * h], Blf[2 * h + 1]);
                    mma_bf16(c, Alf[mt], Bhf[2 * h], Bhf[2 * h + 1]);
                }
        }
        // Refill: all ldsm outputs consumed by issued mma's -> overwrite safe.
        if constexpr (NBUF == 2) {
            if (kc < 6) issueB(kc + 2, kc & 1);
        } else {
            if (kc < 7) issueB(kc + 1, 0);
        }
    }

    // ---------------- epilogue: bias + relu + row l2-norm + store ----------
    const int rg = lane >> 2;
    const int lc = (lane & 3) * 2;

    float bb[2][2];
    #pragma unroll
    for (int g = 0; g < 2; ++g) {
        bb[g][0] = sBias[Nb + g * 8 + lc];
        bb[g][1] = sBias[Nb + g * 8 + lc + 1];
    }

    #pragma unroll
    for (int mt = 0; mt < MT; ++mt)
        #pragma unroll
        for (int rh = 0; rh < 2; ++rh) {
            float ss = 0.f;
            #pragma unroll
            for (int g = 0; g < 2; ++g) {
                float v0 = fmaxf(acc[mt][g][2 * rh]     + bb[g][0], 0.f);
                float v1 = fmaxf(acc[mt][g][2 * rh + 1] + bb[g][1], 0.f);
                acc[mt][g][2 * rh]     = v0;
                acc[mt][g][2 * rh + 1] = v1;
                ss += v0 * v0 + v1 * v1;
            }
            ss += __shfl_xor_sync(0xffffffffu, ss, 1);
            ss += __shfl_xor_sync(0xffffffffu, ss, 2);
            if ((lane & 3) == 0)
                red[warp * BM + mt * 16 + rh * 8 + rg] = ss;
        }
    __syncthreads();

    if (tid < BM) {
        float t = 0.f;
        #pragma unroll
        for (int n = 0; n < 8; ++n) t += red[n * BM + tid];
        sInv[tid] = 1.0f / fmaxf(sqrtf(t), 1e-12f);
    }
    __syncthreads();

    #pragma unroll
    for (int mt = 0; mt < MT; ++mt)
        #pragma unroll
        for (int rh = 0; rh < 2; ++rh) {
            const int row = mt * 16 + rh * 8 + rg;
            const float inv = sInv[row];
            float* orow = out + (size_t)(m0 + row) * 128 + Nb + lc;
            #pragma unroll
            for (int g = 0; g < 2; ++g)
                *(float2*)(orow + g * 8) =
                    make_float2(acc[mt][g][2 * rh] * inv,
                                acc[mt][g][2 * rh + 1] * inv);
        }
}

extern "C" void kernel_launch(void* const* d_in, const int* in_sizes, int n_in,
                              void* d_out, int out_size)
{
    (void)in_sizes; (void)n_in; (void)out_size;

    const float* features = (const float*)d_in[0];
    const float* W0       = (const float*)d_in[1];
    const float* b0       = (const float*)d_in[2];
    const float* W1       = (const float*)d_in[3];
    const float* b1       = (const float*)d_in[4];
    const int*   nodes    = (const int*)d_in[5];
    const int*   nbr1     = (const int*)d_in[6];
    const int*   nbr0     = (const int*)d_in[7];
    float*       out      = (float*)d_out;

    // L0 (BM=32, NBUF=1): 33792 + 20480 + 512 + 1024 + 128 = 55,936 -> occ 4
    // L1 (BM=16, NBUF=2): 16896 + 40960 + 512 +  512 +  64 = 58,944 -> occ 3
    const int SMEM0 = 2 * 32 * AS * 2 + 8 * 1 * BWB + 512 + 8 * 32 * 4 + 32 * 4;
    const int SMEM1 = 2 * 16 * AS * 2 + 8 * 2 * BWB + 512 + 8 * 16 * 4 + 16 * 4;

    cudaFuncSetAttribute(sage_hmma<0, 32, 1>,
                         cudaFuncAttributeMaxDynamicSharedMemorySize, SMEM0);
    cudaFuncSetAttribute(sage_hmma<0, 32, 1>,
                         cudaFuncAttributePreferredSharedMemoryCarveout, 100);
    cudaFuncSetAttribute(sage_hmma<1, 16, 2>,
                         cudaFuncAttributeMaxDynamicSharedMemorySize, SMEM1);
    cudaFuncSetAttribute(sage_hmma<1, 16, 2>,
                         cudaFuncAttributePreferredSharedMemoryCarveout, 100);

    float *h1; __nv_bfloat16 *w0h, *w0l, *w1h, *w1l;
    cudaGetSymbolAddress((void**)&h1,  g_h1);
    cudaGetSymbolAddress((void**)&w0h, g_W0h);
    cudaGetSymbolAddress((void**)&w0l, g_W0l);
    cudaGetSymbolAddress((void**)&w1h, g_W1h);
    cudaGetSymbolAddress((void**)&w1l, g_W1l);

    prep_w<<<128, 128>>>(W0, W1);
    sage_hmma<0, 32, 1><<<L1_ROWS / 32, THREADS, SMEM0>>>(
        features, nodes, nbr1, nbr0, w0h, w0l, b0, h1);
    sage_hmma<1, 16, 2><<<B_TARGETS / 16, THREADS, SMEM1>>>(
        h1, nullptr, nullptr, nullptr, w1h, w1l, b1, out);
}